// round 15
// baseline (speedup 1.0000x reference)
#include <cuda_runtime.h>
#include <cuda_fp16.h>

// Inputs (harness upcasts f16 arrays to f32):
//   x[16384,4096] f32(f16-valued), pairs[8,4096] i32, theta[8,2048] f32,
//   scales[1,4096] f32, out f32.
// Reference rounds to f16 after EVERY op -> *_rn intrinsics, no contraction.
// Chained schedule (rel_err=0.0 since R8): thread keeps one rotation output in
// a register across layers (1 LDS + 1 STS per pair instead of 2+2).
// R15: rotation loop byte-identical to R12 (best: 128.8us). Load/store phases
// restructured into 4-row register chunks (peak regs 48 -> ~34) so that
// launch_bounds(512,3) fits WITHOUT spills -> 3 x 64KB blocks/SM for
// DRAM-phase overlap.
#define DIMV   4096
#define KROT   8
#define GRP    128
#define NGRP   32
#define ILG    64
#define ROWS   8
#define TPB    512

// ---- schedule tables consumed by prep_coef / rot_kernel ----
__device__ unsigned char d_pA[KROT][ILG];     // pair a-channel (ref orientation)
__device__ unsigned char d_pil[KROT][ILG];    // pair handled by slot s at layer k
__device__ unsigned char d_vch[KROT][ILG];    // channel held entering layer k
__device__ unsigned char d_keepv[KROT][ILG];  // keep held-side output?
__device__ unsigned g_pt4[KROT * 16];         // packed READ (partner) channels
__device__ unsigned g_wc4[KROT * 16];         // packed WRITE ch (bit7 = w-neg flag)
__device__ unsigned g_v0p[16];                // packed initial held channels
__device__ unsigned g_v7p[16];                // packed held channels at layer 7
__device__ unsigned g_kv[KROT * ILG * NGRP];  // 4B/entry: (k1,k2) as half2 bits

struct __align__(16) H8 { __half2 r01, r23, r45, r67; };  // 8 rows of a channel

// slot(c,g): conflict-free when lanes span g at warp-uniform c (rotation)
// and when lanes span c>>2 at fixed g (transpose).
__device__ __forceinline__ int slot(int c, int g) {
    return (c << 5) + (g ^ (c >> 2));
}

__device__ __forceinline__ __half2 u2h2(unsigned u) {
    return *reinterpret_cast<__half2*>(&u);
}
__device__ __forceinline__ unsigned h22u(__half2 h) {
    return *reinterpret_cast<unsigned*>(&h);
}

#define NMATCH (KROT - 1)          // 7 matchings
#define NITEM  (NMATCH * GRP)      // 896 (layer, channel) work items

// ---- build chain schedule: one block, fully parallel matching ----
__global__ void __launch_bounds__(TPB)
prep_sched(const int* __restrict__ pairs) {
    __shared__ unsigned char sA[KROT][ILG], sB[KROT][ILG];
    __shared__ unsigned char sOf[KROT][GRP];
    __shared__ unsigned char sNxt[KROT][GRP];     // channel -> partner channel
    __shared__ unsigned char sM[KROT][ILG];
    __shared__ unsigned char sPtr[NMATCH][GRP];   // pointer-doubling succ
    __shared__ unsigned char sRep[NMATCH][GRP];   // orbit min-representative
    __shared__ unsigned char sPil[KROT][ILG], sVch[KROT][ILG], sKeep[KROT][ILG];
    const int tid = threadIdx.x;

    // Phase 1: load all pairs; build lookup tables (512 threads, 1 item each).
    {
        int k = tid >> 6, il = tid & 63;
        int a = pairs[k * DIMV + 2 * il];
        int b = pairs[k * DIMV + 2 * il + 1];
        sA[k][il] = (unsigned char)a;
        sB[k][il] = (unsigned char)b;
        sOf[k][a] = (unsigned char)il;
        sOf[k][b] = (unsigned char)il;
        sNxt[k][a] = (unsigned char)b;
        sNxt[k][b] = (unsigned char)a;
    }
    __syncthreads();

    // Phase 2a: init pointer doubling. succ2(ch) = nxt_k[ nxt_{k+1}[ch] ].
    for (int it = tid; it < NITEM; it += TPB) {
        int k = it >> 7, ch = it & 127;
        sPtr[k][ch] = sNxt[k][sNxt[k + 1][ch]];
        sRep[k][ch] = (unsigned char)ch;
    }
    __syncthreads();

    // Phase 2b: 7 doubling iterations (orbit length <= 64 -> 6 suffice).
    #pragma unroll
    for (int d = 0; d < 7; d++) {
        unsigned char nr[2], np[2];
        int n = 0;
        for (int it = tid; it < NITEM; it += TPB, n++) {
            int k = it >> 7, ch = it & 127;
            int p = sPtr[k][ch];
            unsigned char rp = sRep[k][p];
            unsigned char r  = sRep[k][ch];
            nr[n] = rp < r ? rp : r;
            np[n] = sPtr[k][p];
        }
        __syncthreads();
        n = 0;
        for (int it = tid; it < NITEM; it += TPB, n++) {
            int k = it >> 7, ch = it & 127;
            sRep[k][ch] = nr[n];
            sPtr[k][ch] = np[n];
        }
        __syncthreads();
    }

    // Phase 2c: take the orbit with the smaller representative -> perfect
    // matching (both channels of any pair lie in complementary orbits).
    for (int it = tid; it < NITEM; it += TPB) {
        int k = it >> 7, ch = it & 127;
        int partner_orbit_rep = sRep[k][sNxt[k + 1][ch]];
        if (sRep[k][ch] < partner_orbit_rep)
            sM[k][sOf[k][ch]] = (unsigned char)ch;
    }
    __syncthreads();

    // Phase 3: chains (64 parallel threads; slot s starts at layer-0 pair s).
    if (tid < ILG) {
        const int s = tid;
        int p = s, vch = sA[0][p];
        for (int k = 0; k < KROT; k++) {
            sPil[k][s] = (unsigned char)p;
            sVch[k][s] = (unsigned char)vch;
            if (k < KROT - 1) {
                int kn = sM[k][p];
                sKeep[k][s] = (kn == vch);
                p = sOf[k + 1][kn];
                vch = kn;
            } else sKeep[k][s] = 1;   // layer 7: keep-v form
        }
    }
    __syncthreads();

    // Phase 4: pack warp-uniform tables (128 parallel threads: (k, ilb)).
    if (tid < KROT * 16) {
        int k = tid >> 4, ilb = tid & 15;
        unsigned rv = 0, wv = 0;
        for (int st = 0; st < 4; st++) {
            int s = ilb * 4 + st;
            int pp = sPil[k][s];
            int vch = sVch[k][s];
            int partner = sA[k][pp] ^ sB[k][pp] ^ vch;
            int wc = sKeep[k][s] ? partner : (vch | 0x80);
            rv |= (unsigned)partner << (8 * st);
            wv |= (unsigned)wc << (8 * st);
        }
        g_pt4[tid] = rv;
        g_wc4[tid] = wv;
        if (k == 0) {
            unsigned v0 = 0, v7 = 0;
            for (int st = 0; st < 4; st++) {
                v0 |= (unsigned)sVch[0][ilb * 4 + st] << (8 * st);
                v7 |= (unsigned)sVch[7][ilb * 4 + st] << (8 * st);
            }
            g_v0p[ilb] = v0; g_v7p[ilb] = v7;
        }
    }

    // Phase 5: spill per-(k,slot) tables for prep_coef (512 threads, 1 each).
    {
        int k = tid >> 6, s = tid & 63;
        d_pA[k][s]    = sA[k][s];
        d_pil[k][s]   = sPil[k][s];
        d_vch[k][s]   = sVch[k][s];
        d_keepv[k][s] = sKeep[k][s];
    }
}

// ---- bake per-(layer,slot,group) coefficients, 4B each (64KB, L1-resident) ----
// kv = (k1,k2); write pair = (k2^neg, k1^neg) with neg from g_wc4 bit7.
// keepv:  kv=(c, s'),  neg=0 -> w=(s', c)   (reference forms directly)
// !keepv: kv=(s', -c), neg=1 -> w=(c, -s')  (exact sign-flip identities)
__global__ void prep_coef(const float* __restrict__ theta) {
    int idx = blockIdx.x * blockDim.x + threadIdx.x;
    if (idx >= KROT * ILG * NGRP) return;
    int g = idx & 31, s = (idx >> 5) & 63, k = idx >> 11;
    int p = d_pil[k][s];
    float t = theta[k * 2048 + g * 64 + p];        // theta[k, g*64+il]
    __half c  = __float2half(cosf(t));             // f32 trig, f16 round (ref)
    __half sn = __float2half(sinf(t));
    __half st_ = (d_vch[k][s] == d_pA[k][p]) ? sn : __hneg(sn);
    __half2 kv = d_keepv[k][s] ? __halves2half2(c, st_)
                               : __halves2half2(st_, __hneg(c));
    g_kv[idx] = h22u(kv);                           // idx == (k*64+s)*32+g
}

__global__ void __launch_bounds__(TPB, 3)
rot_kernel(const float* __restrict__ x,
           const float* __restrict__ scales,
           float* __restrict__ out) {
    extern __shared__ H8 W[];                       // 4096 * 16B = 64KB
    const int tid = threadIdx.x;
    const size_t base = (size_t)blockIdx.x * (ROWS * DIMV);

    // ---- Load + transpose: two 4-row register chunks (peak ~32 regs) ----
    #pragma unroll
    for (int qi = 0; qi < 2; qi++) {
        int q = tid + qi * TPB;
        int gg = q >> 5, c0 = (q & 31) * 4;
        const float4* p = (const float4*)(x + base + gg * GRP + c0);
        __half2 h01[4], h23[4], h45[4], h67[4];
        {   // rows 0..3
            float4 v0 = __ldcs(p + 0 * (DIMV / 4));
            float4 v1 = __ldcs(p + 1 * (DIMV / 4));
            float4 v2 = __ldcs(p + 2 * (DIMV / 4));
            float4 v3 = __ldcs(p + 3 * (DIMV / 4));
            const float *f0 = &v0.x, *f1 = &v1.x, *f2 = &v2.x, *f3 = &v3.x;
            #pragma unroll
            for (int j = 0; j < 4; j++) {
                h01[j] = __floats2half2_rn(f0[j], f1[j]);
                h23[j] = __floats2half2_rn(f2[j], f3[j]);
            }
        }
        {   // rows 4..7 (reuses the float4 registers)
            float4 v0 = __ldcs(p + 4 * (DIMV / 4));
            float4 v1 = __ldcs(p + 5 * (DIMV / 4));
            float4 v2 = __ldcs(p + 6 * (DIMV / 4));
            float4 v3 = __ldcs(p + 7 * (DIMV / 4));
            const float *f0 = &v0.x, *f1 = &v1.x, *f2 = &v2.x, *f3 = &v3.x;
            #pragma unroll
            for (int j = 0; j < 4; j++) {
                h45[j] = __floats2half2_rn(f0[j], f1[j]);
                h67[j] = __floats2half2_rn(f2[j], f3[j]);
            }
        }
        #pragma unroll
        for (int j = 0; j < 4; j++) {
            H8 w; w.r01 = h01[j]; w.r23 = h23[j]; w.r45 = h45[j]; w.r67 = h67[j];
            W[slot(c0 + j, gg)] = w;                // STS.128, conflict-free
        }
    }
    __syncthreads();

    // ---- Chained rotation: byte-identical to R12 (proven 128.8us) ----
    const int g   = tid & 31;    // lane = group
    const int ilb = tid >> 5;    // warp = slot quartet

    H8 v[4];
    {
        unsigned v0 = g_v0p[ilb];
        #pragma unroll
        for (int st = 0; st < 4; st++)
            v[st] = W[slot((v0 >> (8 * st)) & 255, g)];
    }

    #pragma unroll
    for (int k = 0; k < KROT; k++) {
        unsigned pt = g_pt4[k * 16 + ilb];          // warp-uniform read channels
        unsigned wt = g_wc4[k * 16 + ilb];          // warp-uniform write ch + negflag
        #pragma unroll
        for (int st = 0; st < 4; st++) {
            int s = ilb * 4 + st;
            unsigned kvu = g_kv[((k * 64 + s) << 5) + g];  // LDG.32, L1-resident
            int pc  = (pt >> (8 * st)) & 255;
            int wcb = (wt >> (8 * st)) & 255;
            int wc  = wcb & 127;
            unsigned nmask = (unsigned)(wcb >> 7) * 0x80008000u;
            H8 w = W[slot(pc, g)];                      // LDS.128 (fresh: non-kept)
            __half2 kv = u2h2(kvu);
            __half2 k1 = __half2half2(__low2half(kv));
            __half2 k2 = __half2half2(__high2half(kv));
            __half2 w1 = u2h2(h22u(k2) ^ nmask);        // exact sign flips
            __half2 w2 = u2h2(h22u(k1) ^ nmask);
            H8 nv, nw;
            nv.r01 = __hsub2_rn(__hmul2_rn(k1, v[st].r01), __hmul2_rn(k2, w.r01));
            nw.r01 = __hadd2_rn(__hmul2_rn(w1, v[st].r01), __hmul2_rn(w2, w.r01));
            nv.r23 = __hsub2_rn(__hmul2_rn(k1, v[st].r23), __hmul2_rn(k2, w.r23));
            nw.r23 = __hadd2_rn(__hmul2_rn(w1, v[st].r23), __hmul2_rn(w2, w.r23));
            nv.r45 = __hsub2_rn(__hmul2_rn(k1, v[st].r45), __hmul2_rn(k2, w.r45));
            nw.r45 = __hadd2_rn(__hmul2_rn(w1, v[st].r45), __hmul2_rn(w2, w.r45));
            nv.r67 = __hsub2_rn(__hmul2_rn(k1, v[st].r67), __hmul2_rn(k2, w.r67));
            nw.r67 = __hadd2_rn(__hmul2_rn(w1, v[st].r67), __hmul2_rn(w2, w.r67));
            W[slot(wc, g)] = nw;                        // STS.128 (non-kept channel)
            v[st] = nv;                                 // register-carried (kept)
        }
        if (k == KROT - 1) {
            unsigned v7 = g_v7p[ilb];
            #pragma unroll
            for (int st = 0; st < 4; st++)
                W[slot((v7 >> (8 * st)) & 255, g)] = v[st];
        }
        __syncthreads();
    }

    // ---- Scale + transpose back + store: 4-row chunks (peak ~36 regs) ----
    #pragma unroll
    for (int qi = 0; qi < 2; qi++) {
        int q = tid + qi * TPB;
        int gg = q >> 5, c0 = (q & 31) * 4;
        int d = gg * GRP + c0;
        float4 sc4 = *(const float4*)(scales + d);
        const float* ps = &sc4.x;
        H8 w[4];
        #pragma unroll
        for (int j = 0; j < 4; j++) w[j] = W[slot(c0 + j, gg)];  // LDS.128 x4
        float4* qp = (float4*)(out + base + d);
        {   // rows 0..3
            float4 o0, o1, o2, o3;
            float *f0 = &o0.x, *f1 = &o1.x, *f2 = &o2.x, *f3 = &o3.x;
            #pragma unroll
            for (int j = 0; j < 4; j++) {
                __half2 sc2 = __half2half2(__float2half(ps[j]));  // exact
                __half2 p01 = __hmul2_rn(w[j].r01, sc2);
                __half2 p23 = __hmul2_rn(w[j].r23, sc2);
                f0[j] = __half2float(__low2half (p01));
                f1[j] = __half2float(__high2half(p01));
                f2[j] = __half2float(__low2half (p23));
                f3[j] = __half2float(__high2half(p23));
            }
            __stcs(qp + 0 * (DIMV / 4), o0);
            __stcs(qp + 1 * (DIMV / 4), o1);
            __stcs(qp + 2 * (DIMV / 4), o2);
            __stcs(qp + 3 * (DIMV / 4), o3);
        }
        {   // rows 4..7 (reuses the float4 registers)
            float4 o0, o1, o2, o3;
            float *f0 = &o0.x, *f1 = &o1.x, *f2 = &o2.x, *f3 = &o3.x;
            #pragma unroll
            for (int j = 0; j < 4; j++) {
                __half2 sc2 = __half2half2(__float2half(ps[j]));  // exact
                __half2 p45 = __hmul2_rn(w[j].r45, sc2);
                __half2 p67 = __hmul2_rn(w[j].r67, sc2);
                f0[j] = __half2float(__low2half (p45));
                f1[j] = __half2float(__high2half(p45));
                f2[j] = __half2float(__low2half (p67));
                f3[j] = __half2float(__high2half(p67));
            }
            __stcs(qp + 4 * (DIMV / 4), o0);
            __stcs(qp + 5 * (DIMV / 4), o1);
            __stcs(qp + 6 * (DIMV / 4), o2);
            __stcs(qp + 7 * (DIMV / 4), o3);
        }
    }
}

extern "C" void kernel_launch(void* const* d_in, const int* in_sizes, int n_in,
                              void* d_out, int out_size) {
    const float* x      = (const float*)d_in[0];
    const int*   pairs  = (const int*)d_in[1];
    const float* theta  = (const float*)d_in[2];
    const float* scales = (const float*)d_in[3];
    (void)n_in; (void)out_size;

    int N = in_sizes[0] / DIMV;   // 16384
    const int smem = DIMV * (int)sizeof(H8);   // 64KB dynamic
    cudaFuncSetAttribute(rot_kernel, cudaFuncAttributeMaxDynamicSharedMemorySize, smem);

    prep_sched<<<1, TPB>>>(pairs);
    prep_coef<<<(KROT * ILG * NGRP + 255) / 256, 256>>>(theta);
    rot_kernel<<<N / ROWS, TPB, smem>>>(x, scales, (float*)d_out);
}

// round 16
// speedup vs baseline: 1.6282x; 1.6282x over previous
#include <cuda_runtime.h>
#include <cuda_fp16.h>

// Inputs (harness upcasts f16 arrays to f32):
//   x[16384,4096] f32(f16-valued), pairs[8,4096] i32, theta[8,2048] f32,
//   scales[1,4096] f32, out f32.
// Reference rounds to f16 after EVERY op -> *_rn intrinsics, no contraction.
// Chained schedule (rel_err=0.0 since R8): thread keeps one rotation output in
// a register across layers (1 LDS + 1 STS per pair instead of 2+2).
// R16: rot_kernel byte-identical to R12 (proven best, 128.8us; min-blocks=3
// falsified twice -> 2 blocks/SM is the operating point). Prep merged into a
// single grid-64 launch: every block redundantly computes the schedule in
// shared (concurrent -> free), block 0 publishes tables, each block computes
// its 256-entry coefficient slice.
#define DIMV   4096
#define KROT   8
#define GRP    128
#define NGRP   32
#define ILG    64
#define ROWS   8
#define TPB    512

// ---- tables consumed by rot_kernel ----
__device__ unsigned g_pt4[KROT * 16];         // packed READ (partner) channels
__device__ unsigned g_wc4[KROT * 16];         // packed WRITE ch (bit7 = w-neg flag)
__device__ unsigned g_v0p[16];                // packed initial held channels
__device__ unsigned g_v7p[16];                // packed held channels at layer 7
__device__ unsigned g_kv[KROT * ILG * NGRP];  // 4B/entry: (k1,k2) as half2 bits

struct __align__(16) H8 { __half2 r01, r23, r45, r67; };  // 8 rows of a channel

// slot(c,g): conflict-free when lanes span g at warp-uniform c (rotation)
// and when lanes span c>>2 at fixed g (transpose).
__device__ __forceinline__ int slot(int c, int g) {
    return (c << 5) + (g ^ (c >> 2));
}

__device__ __forceinline__ __half2 u2h2(unsigned u) {
    return *reinterpret_cast<__half2*>(&u);
}
__device__ __forceinline__ unsigned h22u(__half2 h) {
    return *reinterpret_cast<unsigned*>(&h);
}

#define NMATCH (KROT - 1)          // 7 matchings
#define NITEM  (NMATCH * GRP)      // 896 (layer, channel) work items
#define PREPG  64                  // prep grid: 64 blocks, 256 coefs each

// ---- ONE prep launch: every block computes the schedule (redundant but
// concurrent); block 0 publishes packed tables; each block bakes its slice
// of the coefficient table. All schedule logic identical to R12. ----
__global__ void __launch_bounds__(TPB)
prep_all(const int* __restrict__ pairs, const float* __restrict__ theta) {
    __shared__ unsigned char sA[KROT][ILG], sB[KROT][ILG];
    __shared__ unsigned char sOf[KROT][GRP];
    __shared__ unsigned char sNxt[KROT][GRP];     // channel -> partner channel
    __shared__ unsigned char sM[KROT][ILG];
    __shared__ unsigned char sPtr[NMATCH][GRP];   // pointer-doubling succ
    __shared__ unsigned char sRep[NMATCH][GRP];   // orbit min-representative
    __shared__ unsigned char sPil[KROT][ILG], sVch[KROT][ILG], sKeep[KROT][ILG];
    const int tid = threadIdx.x;

    // Phase 1: load all pairs; build lookup tables (512 threads, 1 item each).
    {
        int k = tid >> 6, il = tid & 63;
        int a = pairs[k * DIMV + 2 * il];
        int b = pairs[k * DIMV + 2 * il + 1];
        sA[k][il] = (unsigned char)a;
        sB[k][il] = (unsigned char)b;
        sOf[k][a] = (unsigned char)il;
        sOf[k][b] = (unsigned char)il;
        sNxt[k][a] = (unsigned char)b;
        sNxt[k][b] = (unsigned char)a;
    }
    __syncthreads();

    // Phase 2a: init pointer doubling. succ2(ch) = nxt_k[ nxt_{k+1}[ch] ].
    // Orbits of succ2 = even/odd positions of the alternating cycle; each
    // cycle contributes exactly 2 complementary orbits.
    for (int it = tid; it < NITEM; it += TPB) {
        int k = it >> 7, ch = it & 127;
        sPtr[k][ch] = sNxt[k][sNxt[k + 1][ch]];
        sRep[k][ch] = (unsigned char)ch;
    }
    __syncthreads();

    // Phase 2b: 7 doubling iterations (orbit length <= 64 -> 6 suffice).
    #pragma unroll
    for (int d = 0; d < 7; d++) {
        unsigned char nr[2], np[2];
        int n = 0;
        for (int it = tid; it < NITEM; it += TPB, n++) {
            int k = it >> 7, ch = it & 127;
            int p = sPtr[k][ch];
            unsigned char rp = sRep[k][p];
            unsigned char r  = sRep[k][ch];
            nr[n] = rp < r ? rp : r;
            np[n] = sPtr[k][p];
        }
        __syncthreads();
        n = 0;
        for (int it = tid; it < NITEM; it += TPB, n++) {
            int k = it >> 7, ch = it & 127;
            sRep[k][ch] = nr[n];
            sPtr[k][ch] = np[n];
        }
        __syncthreads();
    }

    // Phase 2c: take the orbit with the smaller representative -> perfect
    // matching (both channels of any pair lie in complementary orbits).
    for (int it = tid; it < NITEM; it += TPB) {
        int k = it >> 7, ch = it & 127;
        int partner_orbit_rep = sRep[k][sNxt[k + 1][ch]];
        if (sRep[k][ch] < partner_orbit_rep)
            sM[k][sOf[k][ch]] = (unsigned char)ch;
    }
    __syncthreads();

    // Phase 3: chains (64 parallel threads; slot s starts at layer-0 pair s).
    if (tid < ILG) {
        const int s = tid;
        int p = s, vch = sA[0][p];
        for (int k = 0; k < KROT; k++) {
            sPil[k][s] = (unsigned char)p;
            sVch[k][s] = (unsigned char)vch;
            if (k < KROT - 1) {
                int kn = sM[k][p];
                sKeep[k][s] = (kn == vch);
                p = sOf[k + 1][kn];
                vch = kn;
            } else sKeep[k][s] = 1;   // layer 7: keep-v form
        }
    }
    __syncthreads();

    // Phase 4 (block 0 only): pack warp-uniform tables.
    if (blockIdx.x == 0 && tid < KROT * 16) {
        int k = tid >> 4, ilb = tid & 15;
        unsigned rv = 0, wv = 0;
        for (int st = 0; st < 4; st++) {
            int s = ilb * 4 + st;
            int pp = sPil[k][s];
            int vch = sVch[k][s];
            int partner = sA[k][pp] ^ sB[k][pp] ^ vch;
            // read = partner (fresh); write = the non-kept channel;
            // bit7 of write byte = negate both write coefficients (!keepv).
            int wc = sKeep[k][s] ? partner : (vch | 0x80);
            rv |= (unsigned)partner << (8 * st);
            wv |= (unsigned)wc << (8 * st);
        }
        g_pt4[tid] = rv;
        g_wc4[tid] = wv;
        if (k == 0) {
            unsigned v0 = 0, v7 = 0;
            for (int st = 0; st < 4; st++) {
                v0 |= (unsigned)sVch[0][ilb * 4 + st] << (8 * st);
                v7 |= (unsigned)sVch[7][ilb * 4 + st] << (8 * st);
            }
            g_v0p[ilb] = v0; g_v7p[ilb] = v7;
        }
    }

    // Phase 5: coefficient slice, 4B each (64KB total, L1-resident in rot).
    // kv = (k1,k2); write pair = (k2^neg, k1^neg) with neg from g_wc4 bit7.
    // keepv:  kv=(c, s'),  neg=0 -> w=(s', c)   (reference forms directly)
    // !keepv: kv=(s', -c), neg=1 -> w=(c, -s')  (exact sign-flip identities)
    {
        int i = blockIdx.x * (KROT * ILG * NGRP / PREPG) + tid;   // 256/block
        if (tid < KROT * ILG * NGRP / PREPG) {
            int g = i & 31, s = (i >> 5) & 63, k = i >> 11;
            int p = sPil[k][s];
            float t = theta[k * 2048 + g * 64 + p];    // theta[k, g*64+il]
            __half c  = __float2half(cosf(t));         // f32 trig, f16 round (ref)
            __half sn = __float2half(sinf(t));
            __half st_ = (sVch[k][s] == sA[k][p]) ? sn : __hneg(sn);
            __half2 kv = sKeep[k][s] ? __halves2half2(c, st_)
                                     : __halves2half2(st_, __hneg(c));
            g_kv[i] = h22u(kv);                         // i == (k*64+s)*32+g
        }
    }
}

__global__ void __launch_bounds__(TPB, 2)
rot_kernel(const float* __restrict__ x,
           const float* __restrict__ scales,
           float* __restrict__ out) {
    extern __shared__ H8 W[];                       // 4096 * 16B = 64KB
    const int tid = threadIdx.x;
    const size_t base = (size_t)blockIdx.x * (ROWS * DIMV);

    // ---- Load + transpose: streaming global float4 -> channel-major H8 ----
    #pragma unroll
    for (int qi = 0; qi < 2; qi++) {
        int q = tid + qi * TPB;
        int gg = q >> 5, c0 = (q & 31) * 4;
        const float4* p = (const float4*)(x + base + gg * GRP + c0);
        float4 v[8];
        #pragma unroll
        for (int r = 0; r < 8; r++) v[r] = __ldcs(p + r * (DIMV / 4));
        const float* f = &v[0].x;
        #pragma unroll
        for (int j = 0; j < 4; j++) {
            H8 w;
            w.r01 = __floats2half2_rn(f[0*4+j], f[1*4+j]);
            w.r23 = __floats2half2_rn(f[2*4+j], f[3*4+j]);
            w.r45 = __floats2half2_rn(f[4*4+j], f[5*4+j]);
            w.r67 = __floats2half2_rn(f[6*4+j], f[7*4+j]);
            W[slot(c0 + j, gg)] = w;
        }
    }
    __syncthreads();

    // ---- Chained rotation: 4 register-resident chains per thread ----
    const int g   = tid & 31;    // lane = group
    const int ilb = tid >> 5;    // warp = slot quartet

    H8 v[4];
    {
        unsigned v0 = g_v0p[ilb];
        #pragma unroll
        for (int st = 0; st < 4; st++)
            v[st] = W[slot((v0 >> (8 * st)) & 255, g)];
    }

    #pragma unroll
    for (int k = 0; k < KROT; k++) {
        unsigned pt = g_pt4[k * 16 + ilb];          // warp-uniform read channels
        unsigned wt = g_wc4[k * 16 + ilb];          // warp-uniform write ch + negflag
        #pragma unroll
        for (int st = 0; st < 4; st++) {
            int s = ilb * 4 + st;
            unsigned kvu = g_kv[((k * 64 + s) << 5) + g];  // LDG.32, L1-resident
            int pc  = (pt >> (8 * st)) & 255;
            int wcb = (wt >> (8 * st)) & 255;
            int wc  = wcb & 127;
            unsigned nmask = (unsigned)(wcb >> 7) * 0x80008000u;
            H8 w = W[slot(pc, g)];                      // LDS.128 (fresh: non-kept)
            __half2 kv = u2h2(kvu);
            __half2 k1 = __half2half2(__low2half(kv));
            __half2 k2 = __half2half2(__high2half(kv));
            __half2 w1 = u2h2(h22u(k2) ^ nmask);        // exact sign flips
            __half2 w2 = u2h2(h22u(k1) ^ nmask);
            H8 nv, nw;
            nv.r01 = __hsub2_rn(__hmul2_rn(k1, v[st].r01), __hmul2_rn(k2, w.r01));
            nw.r01 = __hadd2_rn(__hmul2_rn(w1, v[st].r01), __hmul2_rn(w2, w.r01));
            nv.r23 = __hsub2_rn(__hmul2_rn(k1, v[st].r23), __hmul2_rn(k2, w.r23));
            nw.r23 = __hadd2_rn(__hmul2_rn(w1, v[st].r23), __hmul2_rn(w2, w.r23));
            nv.r45 = __hsub2_rn(__hmul2_rn(k1, v[st].r45), __hmul2_rn(k2, w.r45));
            nw.r45 = __hadd2_rn(__hmul2_rn(w1, v[st].r45), __hmul2_rn(w2, w.r45));
            nv.r67 = __hsub2_rn(__hmul2_rn(k1, v[st].r67), __hmul2_rn(k2, w.r67));
            nw.r67 = __hadd2_rn(__hmul2_rn(w1, v[st].r67), __hmul2_rn(w2, w.r67));
            W[slot(wc, g)] = nw;                        // STS.128 (non-kept channel)
            v[st] = nv;                                 // register-carried (kept)
        }
        if (k == KROT - 1) {
            unsigned v7 = g_v7p[ilb];
            #pragma unroll
            for (int st = 0; st < 4; st++)
                W[slot((v7 >> (8 * st)) & 255, g)] = v[st];
        }
        __syncthreads();
    }

    // ---- Scale + transpose back + streaming store ----
    #pragma unroll
    for (int qi = 0; qi < 2; qi++) {
        int q = tid + qi * TPB;
        int gg = q >> 5, c0 = (q & 31) * 4;
        int d = gg * GRP + c0;
        float4 sc4 = *(const float4*)(scales + d);
        const float* ps = &sc4.x;
        float o[8][4];
        #pragma unroll
        for (int j = 0; j < 4; j++) {
            H8 w = W[slot(c0 + j, gg)];
            __half2 sc2 = __half2half2(__float2half(ps[j]));  // exact
            __half2 p01 = __hmul2_rn(w.r01, sc2);
            __half2 p23 = __hmul2_rn(w.r23, sc2);
            __half2 p45 = __hmul2_rn(w.r45, sc2);
            __half2 p67 = __hmul2_rn(w.r67, sc2);
            o[0][j] = __half2float(__low2half (p01));
            o[1][j] = __half2float(__high2half(p01));
            o[2][j] = __half2float(__low2half (p23));
            o[3][j] = __half2float(__high2half(p23));
            o[4][j] = __half2float(__low2half (p45));
            o[5][j] = __half2float(__high2half(p45));
            o[6][j] = __half2float(__low2half (p67));
            o[7][j] = __half2float(__high2half(p67));
        }
        float4* qp = (float4*)(out + base + d);
        #pragma unroll
        for (int r = 0; r < ROWS; r++)
            __stcs(qp + r * (DIMV / 4),
                   make_float4(o[r][0], o[r][1], o[r][2], o[r][3]));
    }
}

extern "C" void kernel_launch(void* const* d_in, const int* in_sizes, int n_in,
                              void* d_out, int out_size) {
    const float* x      = (const float*)d_in[0];
    const int*   pairs  = (const int*)d_in[1];
    const float* theta  = (const float*)d_in[2];
    const float* scales = (const float*)d_in[3];
    (void)n_in; (void)out_size;

    int N = in_sizes[0] / DIMV;   // 16384
    const int smem = DIMV * (int)sizeof(H8);   // 64KB dynamic
    cudaFuncSetAttribute(rot_kernel, cudaFuncAttributeMaxDynamicSharedMemorySize, smem);

    prep_all<<<PREPG, TPB>>>(pairs, theta);
    rot_kernel<<<N / ROWS, TPB, smem>>>(x, scales, (float*)d_out);
}

// round 17
// speedup vs baseline: 1.7414x; 1.0696x over previous
#include <cuda_runtime.h>
#include <cuda_fp16.h>

// Inputs (harness upcasts f16 arrays to f32):
//   x[16384,4096] f32(f16-valued), pairs[8,4096] i32, theta[8,2048] f32,
//   scales[1,4096] f32, out f32.
// Reference rounds to f16 after EVERY op -> *_rn intrinsics, no contraction.
// Chained schedule (rel_err=0.0 since R8): thread keeps one rotation output in
// a register across layers (1 LDS + 1 STS per pair instead of 2+2).
// R17: tiles split across the GROUP axis (8 rows x 16 groups, 32KB) -> FOUR
// blocks/SM at the same 64-reg budget (4x256 thr x 64 = full regfile). More
// co-resident blocks = phase diversity = DRAM busy during rotation phases.
// Index tables now store precomputed slot BASES: slot16(c,g) = b16(c) XOR g
// (exact; low-4 bits of c*16 are zero), so per-step addressing is bfe+xor.
#define DIMV   4096
#define KROT   8
#define GRP    128
#define NGRP   32
#define ILG    64
#define ROWS   8
#define TPB    256          // rot kernel: 8 warps
#define PTPB   512          // prep kernel
#define TGRP   16           // groups per tile
#define TCH    (TGRP * GRP) // 2048 channels per tile

// ---- tables consumed by rot_kernel ----
__device__ unsigned g_ads[KROT * ILG];        // per (k,slot): rd_base12 | wr_base12<<12 | neg<<24
__device__ unsigned g_v0p[16];                // packed initial held channels (per quartet)
__device__ unsigned g_v7p[16];                // packed held channels at layer 7
__device__ unsigned g_kv[KROT * ILG * NGRP];  // 4B/entry: (k1,k2) as half2 bits

struct __align__(16) H8 { __half2 r01, r23, r45, r67; };  // 8 rows of a channel

// b16(c): slot base for the 16-group tile; slot16(c,g) = b16(c) ^ g (g<16).
// Conflict-free: rotation (c uniform per half-warp, g spans 0..15) and
// transpose (g uniform, c=4l+j) both give addr mod 8 = xor-term mod 8 distinct
// per 8-lane phase.
__device__ __host__ __forceinline__ int b16(int c) {
    return (c << 4) + ((c >> 2) & 15);
}

__device__ __forceinline__ __half2 u2h2(unsigned u) {
    return *reinterpret_cast<__half2*>(&u);
}
__device__ __forceinline__ unsigned h22u(__half2 h) {
    return *reinterpret_cast<unsigned*>(&h);
}

#define NMATCH (KROT - 1)
#define NITEM  (NMATCH * GRP)
#define PREPG  64            // prep grid: 64 blocks, 256 coefs each

// ---- ONE prep launch: every block computes the schedule (redundant but
// concurrent); block 0 publishes index tables; each block bakes its slice
// of the coefficient table. Schedule logic identical to R12/R16. ----
__global__ void __launch_bounds__(PTPB)
prep_all(const int* __restrict__ pairs, const float* __restrict__ theta) {
    __shared__ unsigned char sA[KROT][ILG], sB[KROT][ILG];
    __shared__ unsigned char sOf[KROT][GRP];
    __shared__ unsigned char sNxt[KROT][GRP];
    __shared__ unsigned char sM[KROT][ILG];
    __shared__ unsigned char sPtr[NMATCH][GRP];
    __shared__ unsigned char sRep[NMATCH][GRP];
    __shared__ unsigned char sPil[KROT][ILG], sVch[KROT][ILG], sKeep[KROT][ILG];
    const int tid = threadIdx.x;

    // Phase 1: load all pairs; build lookup tables.
    {
        int k = tid >> 6, il = tid & 63;
        int a = pairs[k * DIMV + 2 * il];
        int b = pairs[k * DIMV + 2 * il + 1];
        sA[k][il] = (unsigned char)a;
        sB[k][il] = (unsigned char)b;
        sOf[k][a] = (unsigned char)il;
        sOf[k][b] = (unsigned char)il;
        sNxt[k][a] = (unsigned char)b;
        sNxt[k][b] = (unsigned char)a;
    }
    __syncthreads();

    // Phase 2a: pointer-doubling init. succ2(ch) = nxt_k[nxt_{k+1}[ch]].
    for (int it = tid; it < NITEM; it += PTPB) {
        int k = it >> 7, ch = it & 127;
        sPtr[k][ch] = sNxt[k][sNxt[k + 1][ch]];
        sRep[k][ch] = (unsigned char)ch;
    }
    __syncthreads();

    // Phase 2b: 7 doubling iterations.
    #pragma unroll
    for (int d = 0; d < 7; d++) {
        unsigned char nr[2], np[2];
        int n = 0;
        for (int it = tid; it < NITEM; it += PTPB, n++) {
            int k = it >> 7, ch = it & 127;
            int p = sPtr[k][ch];
            unsigned char rp = sRep[k][p];
            unsigned char r  = sRep[k][ch];
            nr[n] = rp < r ? rp : r;
            np[n] = sPtr[k][p];
        }
        __syncthreads();
        n = 0;
        for (int it = tid; it < NITEM; it += PTPB, n++) {
            int k = it >> 7, ch = it & 127;
            sRep[k][ch] = nr[n];
            sPtr[k][ch] = np[n];
        }
        __syncthreads();
    }

    // Phase 2c: orbit with smaller representative -> perfect matching.
    for (int it = tid; it < NITEM; it += PTPB) {
        int k = it >> 7, ch = it & 127;
        int pr = sRep[k][sNxt[k + 1][ch]];
        if (sRep[k][ch] < pr)
            sM[k][sOf[k][ch]] = (unsigned char)ch;
    }
    __syncthreads();

    // Phase 3: chains (64 parallel threads).
    if (tid < ILG) {
        const int s = tid;
        int p = s, vch = sA[0][p];
        for (int k = 0; k < KROT; k++) {
            sPil[k][s] = (unsigned char)p;
            sVch[k][s] = (unsigned char)vch;
            if (k < KROT - 1) {
                int kn = sM[k][p];
                sKeep[k][s] = (kn == vch);
                p = sOf[k + 1][kn];
                vch = kn;
            } else sKeep[k][s] = 1;
        }
    }
    __syncthreads();

    // Phase 4 (block 0): per-(k,slot) address word with precomputed slot bases,
    // plus packed v0/v7 channels per quartet.
    if (blockIdx.x == 0 && tid < KROT * ILG) {
        int k = tid >> 6, s = tid & 63;
        int pp = sPil[k][s];
        int vch = sVch[k][s];
        int partner = sA[k][pp] ^ sB[k][pp] ^ vch;
        int wr_c = sKeep[k][s] ? partner : vch;   // non-kept channel's slot
        int neg  = sKeep[k][s] ? 0 : 1;           // negate write coefficients
        g_ads[tid] = (unsigned)b16(partner) | ((unsigned)b16(wr_c) << 12)
                   | ((unsigned)neg << 24);
        if (k == 0 && (s & 3) == 0) {
            int q = s >> 2;
            unsigned v0 = 0, v7 = 0;
            for (int st = 0; st < 4; st++) {
                v0 |= (unsigned)sVch[0][q * 4 + st] << (8 * st);
                v7 |= (unsigned)sVch[7][q * 4 + st] << (8 * st);
            }
            g_v0p[q] = v0; g_v7p[q] = v7;
        }
    }

    // Phase 5: coefficient slice, 4B each (64KB total).
    // kv=(k1,k2); write pair = (k2^neg, k1^neg).
    // keepv:  kv=(c, s'),  neg=0;  !keepv: kv=(s', -c), neg=1. (bit-exact)
    {
        int i = blockIdx.x * (KROT * ILG * NGRP / PREPG) + tid;   // 256/block
        if (tid < KROT * ILG * NGRP / PREPG) {
            int g = i & 31, s = (i >> 5) & 63, k = i >> 11;
            int p = sPil[k][s];
            float t = theta[k * 2048 + g * 64 + p];
            __half c  = __float2half(cosf(t));
            __half sn = __float2half(sinf(t));
            __half st_ = (sVch[k][s] == sA[k][p]) ? sn : __hneg(sn);
            __half2 kv = sKeep[k][s] ? __halves2half2(c, st_)
                                     : __halves2half2(st_, __hneg(c));
            g_kv[i] = h22u(kv);
        }
    }
}

__global__ void __launch_bounds__(TPB, 4)
rot_kernel(const float* __restrict__ x,
           const float* __restrict__ scales,
           float* __restrict__ out) {
    extern __shared__ H8 W[];                    // 2048 * 16B = 32KB
    const int tid  = threadIdx.x;
    const int lane = tid & 31;
    const int wid  = tid >> 5;                   // 0..7
    const int lg   = lane & 15;                  // local group 0..15
    const int q    = wid * 2 + (lane >> 4);      // slot quartet 0..15

    const int half = blockIdx.x & 1;             // which 16-group half
    const int rowt = blockIdx.x >> 1;            // row tile
    const size_t base = (size_t)rowt * (ROWS * DIMV) + (size_t)half * TCH;
    const int gofs = half * TGRP;                // global group offset for coefs

    // ---- Load + transpose: streaming float4 -> channel-major H8 (32KB) ----
    #pragma unroll
    for (int qi = 0; qi < 2; qi++) {
        int Q = tid + qi * TPB;                  // quad 0..511
        int gg = Q >> 5, c0 = (Q & 31) * 4;      // local group, channel base
        const float4* p = (const float4*)(x + base + gg * GRP + c0);
        float4 v[8];
        #pragma unroll
        for (int r = 0; r < 8; r++) v[r] = __ldcs(p + r * (DIMV / 4));
        const float* f = &v[0].x;
        #pragma unroll
        for (int j = 0; j < 4; j++) {
            H8 w;
            w.r01 = __floats2half2_rn(f[0*4+j], f[1*4+j]);
            w.r23 = __floats2half2_rn(f[2*4+j], f[3*4+j]);
            w.r45 = __floats2half2_rn(f[4*4+j], f[5*4+j]);
            w.r67 = __floats2half2_rn(f[6*4+j], f[7*4+j]);
            W[b16(c0 + j) ^ gg] = w;             // STS.128, conflict-free
        }
    }
    __syncthreads();

    // ---- Chained rotation: 4 register-resident chains per thread ----
    H8 v[4];
    {
        unsigned v0 = g_v0p[q];
        #pragma unroll
        for (int st = 0; st < 4; st++)
            v[st] = W[b16((v0 >> (8 * st)) & 255) ^ lg];
    }

    #pragma unroll
    for (int k = 0; k < KROT; k++) {
        #pragma unroll
        for (int st = 0; st < 4; st++) {
            int s = q * 4 + st;
            unsigned ad = g_ads[k * 64 + s];             // uniform per half-warp
            unsigned kvu = g_kv[((k * 64 + s) << 5) + gofs + lg];  // L1-resident
            unsigned nmask = (ad >> 24) * 0x80008000u;
            H8 w = W[(int)(ad & 0xFFF) ^ lg];            // LDS.128 (fresh)
            __half2 kv = u2h2(kvu);
            __half2 k1 = __half2half2(__low2half(kv));
            __half2 k2 = __half2half2(__high2half(kv));
            __half2 w1 = u2h2(h22u(k2) ^ nmask);         // exact sign flips
            __half2 w2 = u2h2(h22u(k1) ^ nmask);
            H8 nv, nw;
            nv.r01 = __hsub2_rn(__hmul2_rn(k1, v[st].r01), __hmul2_rn(k2, w.r01));
            nw.r01 = __hadd2_rn(__hmul2_rn(w1, v[st].r01), __hmul2_rn(w2, w.r01));
            nv.r23 = __hsub2_rn(__hmul2_rn(k1, v[st].r23), __hmul2_rn(k2, w.r23));
            nw.r23 = __hadd2_rn(__hmul2_rn(w1, v[st].r23), __hmul2_rn(w2, w.r23));
            nv.r45 = __hsub2_rn(__hmul2_rn(k1, v[st].r45), __hmul2_rn(k2, w.r45));
            nw.r45 = __hadd2_rn(__hmul2_rn(w1, v[st].r45), __hmul2_rn(w2, w.r45));
            nv.r67 = __hsub2_rn(__hmul2_rn(k1, v[st].r67), __hmul2_rn(k2, w.r67));
            nw.r67 = __hadd2_rn(__hmul2_rn(w1, v[st].r67), __hmul2_rn(w2, w.r67));
            W[(int)((ad >> 12) & 0xFFF) ^ lg] = nw;      // STS.128 (non-kept)
            v[st] = nv;                                  // register-carried (kept)
        }
        if (k == KROT - 1) {
            unsigned v7 = g_v7p[q];
            #pragma unroll
            for (int st = 0; st < 4; st++)
                W[b16((v7 >> (8 * st)) & 255) ^ lg] = v[st];
        }
        __syncthreads();
    }

    // ---- Scale + transpose back + streaming store ----
    #pragma unroll
    for (int qi = 0; qi < 2; qi++) {
        int Q = tid + qi * TPB;
        int gg = Q >> 5, c0 = (Q & 31) * 4;
        int dloc = gg * GRP + c0;                         // within-tile channel
        float4 sc4 = *(const float4*)(scales + half * TCH + dloc);
        const float* ps = &sc4.x;
        float o[8][4];
        #pragma unroll
        for (int j = 0; j < 4; j++) {
            H8 w = W[b16(c0 + j) ^ gg];
            __half2 sc2 = __half2half2(__float2half(ps[j]));  // exact
            __half2 p01 = __hmul2_rn(w.r01, sc2);
            __half2 p23 = __hmul2_rn(w.r23, sc2);
            __half2 p45 = __hmul2_rn(w.r45, sc2);
            __half2 p67 = __hmul2_rn(w.r67, sc2);
            o[0][j] = __half2float(__low2half (p01));
            o[1][j] = __half2float(__high2half(p01));
            o[2][j] = __half2float(__low2half (p23));
            o[3][j] = __half2float(__high2half(p23));
            o[4][j] = __half2float(__low2half (p45));
            o[5][j] = __half2float(__high2half(p45));
            o[6][j] = __half2float(__low2half (p67));
            o[7][j] = __half2float(__high2half(p67));
        }
        float4* qp = (float4*)(out + base + dloc);
        #pragma unroll
        for (int r = 0; r < 8; r++)
            __stcs(qp + r * (DIMV / 4),
                   make_float4(o[r][0], o[r][1], o[r][2], o[r][3]));
    }
}

extern "C" void kernel_launch(void* const* d_in, const int* in_sizes, int n_in,
                              void* d_out, int out_size) {
    const float* x      = (const float*)d_in[0];
    const int*   pairs  = (const int*)d_in[1];
    const float* theta  = (const float*)d_in[2];
    const float* scales = (const float*)d_in[3];
    (void)n_in; (void)out_size;

    int N = in_sizes[0] / DIMV;   // 16384
    const int smem = TCH * (int)sizeof(H8);   // 32KB dynamic
    cudaFuncSetAttribute(rot_kernel, cudaFuncAttributeMaxDynamicSharedMemorySize, smem);

    prep_all<<<PREPG, PTPB>>>(pairs, theta);
    rot_kernel<<<(N / ROWS) * 2, TPB, smem>>>(x, scales, (float*)d_out);
}